// round 14
// baseline (speedup 1.0000x reference)
#include <cuda_runtime.h>
#include <cuda_fp16.h>
#include <cstdint>

// ============================================================================
// LinearAttentionLayer B=16,N=8192,F=128,U=128 fp32.
// Round 14: stage A -> 2 CTAs/SM (grid 296, lb(256,2)). Round-13 shrank A's
// smem to 115.7KB so two fit per SM; the x register-prefetch (32 regs) is
// dropped to fit the 128-reg budget — cross-CTA overlap now hides the DRAM
// and phase latency the prefetch + 2-warp/SMSP occupancy couldn't.
// All GEMMs remain single-pass fp16 (storage roundings dominate error).
// ============================================================================

namespace {
constexpr int Bb = 16, Nn = 8192;
constexpr int SUBT = 64;
constexpr int TASKS = Bb * (Nn / SUBT);   // 2048
constexpr int GRIDA = 296;                // 2 CTAs/SM
constexpr int GRIDB = 296;                // 2 CTAs/SM

// stage A smem (bytes): all hi-only
constexpr int SA_WKH = 0;            // 128x128 fp16 = 32768
constexpr int SA_WVH = 32768;
constexpr int SA_XH  = 65536;        // 64x128 fp16 = 16384
constexpr int SA_KH  = 81920;
constexpr int SA_VH  = 98304;
constexpr int SA_BK  = 114688, SA_BV = 115200;
constexpr int SA_SMEM = 115712;      // x2 = 231424 <= 228KB/SM

// stage B smem
constexpr int SB_WQH = 0;
constexpr int SB_KVH = 32768;
constexpr int SB_XH  = 65536;
constexpr int SB_QH  = 81920;
constexpr int SB_BQ  = 98304;
constexpr int SB_SMEM = 98816;       // x2 = 197632
}

__device__ float g_kv[Bb * 128 * 128];

// ---------------------------------------------------------------------------
__device__ __forceinline__ uint32_t smem_u32(const void* p) {
    uint32_t a;
    asm("{ .reg .u64 t; cvta.to.shared.u64 t, %1; cvt.u32.u64 %0, t; }" : "=r"(a) : "l"(p));
    return a;
}
__device__ __forceinline__ uint32_t swz(uint32_t row, uint32_t cb) {
    return row * 256u + (cb & 0x80u) + ((cb & 0x7Fu) ^ ((row & 7u) << 4));
}
__device__ __forceinline__ void ldsm4(uint32_t a, uint32_t* r) {
    asm volatile("ldmatrix.sync.aligned.m8n8.x4.shared.b16 {%0,%1,%2,%3}, [%4];"
        : "=r"(r[0]), "=r"(r[1]), "=r"(r[2]), "=r"(r[3]) : "r"(a));
}
__device__ __forceinline__ void ldsm4t(uint32_t a, uint32_t* r) {
    asm volatile("ldmatrix.sync.aligned.m8n8.x4.trans.shared.b16 {%0,%1,%2,%3}, [%4];"
        : "=r"(r[0]), "=r"(r[1]), "=r"(r[2]), "=r"(r[3]) : "r"(a));
}
__device__ __forceinline__ void mma16816f(float* d, const uint32_t* a, const uint32_t* b) {
    asm volatile(
        "mma.sync.aligned.m16n8k16.row.col.f32.f16.f16.f32 "
        "{%0,%1,%2,%3}, {%4,%5,%6,%7}, {%8,%9}, {%0,%1,%2,%3};"
        : "+f"(d[0]), "+f"(d[1]), "+f"(d[2]), "+f"(d[3])
        : "r"(a[0]), "r"(a[1]), "r"(a[2]), "r"(a[3]), "r"(b[0]), "r"(b[1]));
}
// 1-pass 16x16
__device__ __forceinline__ void mma1(float* d0, float* d1,
    const uint32_t* ah, const uint32_t* bh) {
    mma16816f(d0, ah, bh); mma16816f(d1, ah, bh + 2);
}

__device__ __forceinline__ uint32_t pack16(float v0, float v1) {
    __half2 h = __floats2half2_rn(v0, v1);
    return *reinterpret_cast<uint32_t*>(&h);
}

__device__ __forceinline__ float fexp(float x) {
    float t = x * 1.4426950408889634f;
    float r = t + 12582912.0f;
    int   e = __float_as_int(r) - 0x4B400000;
    float y = (t - (r - 12582912.0f)) * 0.6931471805599453f;
    float p = 1.38888894e-3f;
    p = fmaf(p, y, 8.33333377e-3f);
    p = fmaf(p, y, 4.16666679e-2f);
    p = fmaf(p, y, 1.66666672e-1f);
    p = fmaf(p, y, 0.5f);
    p = fmaf(p, y, 1.0f);
    p = fmaf(p, y, 1.0f);
    return __int_as_float(__float_as_int(p) + (e << 23));
}

__global__ void zero_kv_kernel() {
    int i = blockIdx.x * blockDim.x + threadIdx.x;
    reinterpret_cast<float4*>(g_kv)[i] = make_float4(0.f, 0.f, 0.f, 0.f);
}

// direct gmem -> fp16 smem (no register staging; 2-CTA overlap hides latency)
__device__ __forceinline__ void load_x_direct(
    char* smem, int XHo, const float4* xsrc, int tid)
{
    #pragma unroll
    for (int ii = 0; ii < 8; ++ii) {
        int i = tid + ii * 256;
        uint32_t r  = (uint32_t)(i >> 5);
        uint32_t cb = (uint32_t)(i & 31) * 8;
        float4 v = xsrc[i];
        *(uint2*)(smem + XHo + swz(r, cb)) =
            make_uint2(pack16(v.x, v.y), pack16(v.z, v.w));
    }
}

// ===========================================================================
// Stage A — 2 CTAs/SM
// ===========================================================================
__global__ void __launch_bounds__(256, 2) stageA(
    const float* __restrict__ x,
    const float* __restrict__ Wk, const float* __restrict__ bk,
    const float* __restrict__ Wv, const float* __restrict__ bv)
{
    extern __shared__ char smem[];
    const uint32_t sb = smem_u32(smem);
    const int tid = threadIdx.x, warp = tid >> 5, lane = tid & 31;

    const int task0 = (int)((long)blockIdx.x * TASKS / GRIDA);
    const int task1 = (int)((long)(blockIdx.x + 1) * TASKS / GRIDA);

    // W (hi only) into swizzled smem
    {
        const float2* wk2 = reinterpret_cast<const float2*>(Wk);
        const float2* wv2 = reinterpret_cast<const float2*>(Wv);
        for (int i = tid; i < 8192; i += 256) {
            uint32_t f  = (uint32_t)(i >> 6);
            uint32_t cb = (uint32_t)(i & 63) * 4;
            float2 a = wk2[i];
            *(uint32_t*)(smem + SA_WKH + swz(f, cb)) = pack16(a.x, a.y);
            a = wv2[i];
            *(uint32_t*)(smem + SA_WVH + swz(f, cb)) = pack16(a.x, a.y);
        }
        if (tid < 128) {
            ((float*)(smem + SA_BK))[tid] = bk[tid];
            ((float*)(smem + SA_BV))[tid] = bv[tid];
        }
    }

    const int pm0 = (warp >> 2) * 32, pc0 = (warp & 3) * 32;
    const int u0  = (warp & 3) * 32,  w0  = (warp >> 2) * 64;
    const int er = lane >> 2, ec = 2 * (lane & 3);

    float kvacc[2][8][4];
    #pragma unroll
    for (int mb = 0; mb < 2; ++mb)
        #pragma unroll
        for (int nb = 0; nb < 8; ++nb)
            kvacc[mb][nb][0] = kvacc[mb][nb][1] = kvacc[mb][nb][2] = kvacc[mb][nb][3] = 0.f;

    const float* sbk = (const float*)(smem + SA_BK);
    const float* sbv = (const float*)(smem + SA_BV);
    const float4* xall = reinterpret_cast<const float4*>(x);

    int bcur = task0 >> 7;
    for (int t = task0; t < task1; ++t) {
        const int b = t >> 7;
        if (b != bcur) {
            float* kvb = g_kv + (size_t)bcur * 16384;
            #pragma unroll
            for (int mb = 0; mb < 2; ++mb) {
                int ur = u0 + mb * 16 + er;
                #pragma unroll
                for (int nb = 0; nb < 8; ++nb) {
                    int col = w0 + nb * 8 + ec;
                    atomicAdd(&kvb[ur * 128 + col],           kvacc[mb][nb][0]);
                    atomicAdd(&kvb[ur * 128 + col + 1],       kvacc[mb][nb][1]);
                    atomicAdd(&kvb[(ur + 8) * 128 + col],     kvacc[mb][nb][2]);
                    atomicAdd(&kvb[(ur + 8) * 128 + col + 1], kvacc[mb][nb][3]);
                    kvacc[mb][nb][0] = kvacc[mb][nb][1] = kvacc[mb][nb][2] = kvacc[mb][nb][3] = 0.f;
                }
            }
            bcur = b;
        }

        load_x_direct(smem, SA_XH, xall + (size_t)t * 2048, tid);
        __syncthreads();   // X ready; all warps done with prior kv phase

        // ---- fused K/V projection (1-pass), warp tile 32x32 ----
        float ka[2][4][4], va[2][4][4];
        #pragma unroll
        for (int mb = 0; mb < 2; ++mb)
            #pragma unroll
            for (int nb = 0; nb < 4; ++nb) {
                ka[mb][nb][0] = ka[mb][nb][1] = ka[mb][nb][2] = ka[mb][nb][3] = 0.f;
                va[mb][nb][0] = va[mb][nb][1] = va[mb][nb][2] = va[mb][nb][3] = 0.f;
            }
        {
            const uint32_t arow0 = (uint32_t)(pm0 + (lane & 15));
            const uint32_t aco   = (uint32_t)((lane >> 4) & 1) * 16;
            const uint32_t brl   = (uint32_t)(lane & 15);
            #pragma unroll
            for (int ks = 0; ks < 8; ++ks) {
                uint32_t ah[2][4];
                uint32_t acb = (uint32_t)ks * 32 + aco;
                ldsm4(sb + SA_XH + swz(arow0,      acb), ah[0]);
                ldsm4(sb + SA_XH + swz(arow0 + 16, acb), ah[1]);
                #pragma unroll
                for (int ng = 0; ng < 2; ++ng) {
                    uint32_t br  = (uint32_t)ks * 16 + brl;
                    uint32_t bcb = (uint32_t)(pc0 + ng * 16) * 2 + aco;
                    uint32_t bh[4];
                    ldsm4t(sb + SA_WKH + swz(br, bcb), bh);
                    mma1(ka[0][2 * ng], ka[0][2 * ng + 1], ah[0], bh);
                    mma1(ka[1][2 * ng], ka[1][2 * ng + 1], ah[1], bh);
                    ldsm4t(sb + SA_WVH + swz(br, bcb), bh);
                    mma1(va[0][2 * ng], va[0][2 * ng + 1], ah[0], bh);
                    mma1(va[1][2 * ng], va[1][2 * ng + 1], ah[1], bh);
                }
            }
        }
        // ---- epilogue: k=exp(.+bk), v=.+bv -> hi smem ----
        #pragma unroll
        for (int mb = 0; mb < 2; ++mb) {
            int r0 = pm0 + mb * 16 + er;
            #pragma unroll
            for (int nb = 0; nb < 4; ++nb) {
                int col = pc0 + nb * 8 + ec;
                float bk0 = sbk[col], bk1 = sbk[col + 1];
                float bv0 = sbv[col], bv1 = sbv[col + 1];
                *(uint32_t*)(smem + SA_KH + swz((uint32_t)r0, (uint32_t)col * 2)) =
                    pack16(fexp(ka[mb][nb][0] + bk0), fexp(ka[mb][nb][1] + bk1));
                *(uint32_t*)(smem + SA_KH + swz((uint32_t)(r0 + 8), (uint32_t)col * 2)) =
                    pack16(fexp(ka[mb][nb][2] + bk0), fexp(ka[mb][nb][3] + bk1));
                *(uint32_t*)(smem + SA_VH + swz((uint32_t)r0, (uint32_t)col * 2)) =
                    pack16(va[mb][nb][0] + bv0, va[mb][nb][1] + bv1);
                *(uint32_t*)(smem + SA_VH + swz((uint32_t)(r0 + 8), (uint32_t)col * 2)) =
                    pack16(va[mb][nb][2] + bv0, va[mb][nb][3] + bv1);
            }
        }
        __syncthreads();   // K/V ready

        // ---- kv += k^T v (1-pass), warp tile 32u x 64w ----
        {
            const uint32_t krl = (uint32_t)(((lane >> 4) & 1) * 8 + (lane & 7));
            const uint32_t vco = (uint32_t)((lane >> 4) & 1) * 16;
            #pragma unroll
            for (int ks = 0; ks < 4; ++ks) {
                uint32_t kah[2][4];
                uint32_t kr = (uint32_t)ks * 16 + krl;
                #pragma unroll
                for (int mb = 0; mb < 2; ++mb) {
                    uint32_t ucb = (uint32_t)(u0 + mb * 16 + ((lane >> 3) & 1) * 8) * 2;
                    ldsm4t(sb + SA_KH + swz(kr, ucb), kah[mb]);
                }
                #pragma unroll
                for (int ng = 0; ng < 4; ++ng) {
                    uint32_t vr  = (uint32_t)(ks * 16 + (lane & 15));
                    uint32_t vcb = (uint32_t)(w0 + ng * 16) * 2 + vco;
                    uint32_t bh[4];
                    ldsm4t(sb + SA_VH + swz(vr, vcb), bh);
                    mma1(kvacc[0][2 * ng], kvacc[0][2 * ng + 1], kah[0], bh);
                    mma1(kvacc[1][2 * ng], kvacc[1][2 * ng + 1], kah[1], bh);
                }
            }
        }
    }

    // final flush
    {
        float* kvb = g_kv + (size_t)bcur * 16384;
        #pragma unroll
        for (int mb = 0; mb < 2; ++mb) {
            int ur = u0 + mb * 16 + er;
            #pragma unroll
            for (int nb = 0; nb < 8; ++nb) {
                int col = w0 + nb * 8 + ec;
                atomicAdd(&kvb[ur * 128 + col],           kvacc[mb][nb][0]);
                atomicAdd(&kvb[ur * 128 + col + 1],       kvacc[mb][nb][1]);
                atomicAdd(&kvb[(ur + 8) * 128 + col],     kvacc[mb][nb][2]);
                atomicAdd(&kvb[(ur + 8) * 128 + col + 1], kvacc[mb][nb][3]);
            }
        }
    }
}

// ===========================================================================
// Stage B — 2 CTAs/SM
// ===========================================================================
__global__ void __launch_bounds__(256, 2) stageB(
    const float* __restrict__ x,
    const float* __restrict__ Wq, const float* __restrict__ bq,
    float* __restrict__ out)
{
    extern __shared__ char smem[];
    const uint32_t sb = smem_u32(smem);
    const int tid = threadIdx.x, warp = tid >> 5, lane = tid & 31;

    const int task0 = (int)((long)blockIdx.x * TASKS / GRIDB);
    const int task1 = (int)((long)(blockIdx.x + 1) * TASKS / GRIDB);

    {
        const float2* wq2 = reinterpret_cast<const float2*>(Wq);
        for (int i = tid; i < 8192; i += 256) {
            uint32_t f  = (uint32_t)(i >> 6);
            uint32_t cb = (uint32_t)(i & 63) * 4;
            float2 a = wq2[i];
            *(uint32_t*)(smem + SB_WQH + swz(f, cb)) = pack16(a.x, a.y);
        }
        if (tid < 128)
            ((float*)(smem + SB_BQ))[tid] = bq[tid];
    }

    const int m0 = (warp >> 2) * 32, c0 = (warp & 3) * 32;
    const int er = lane >> 2, ec = 2 * (lane & 3);
    const float* sbq = (const float*)(smem + SB_BQ);
    const float4* xall = reinterpret_cast<const float4*>(x);

    float4 xr[8];
    #pragma unroll
    for (int ii = 0; ii < 8; ++ii)
        xr[ii] = xall[(size_t)task0 * 2048 + ii * 256 + tid];

    int bcur = -1;
    for (int t = task0; t < task1; ++t) {
        const int b = t >> 7;

        // store prefetched x, then prefetch next
        #pragma unroll
        for (int ii = 0; ii < 8; ++ii) {
            int i = tid + ii * 256;
            uint32_t r  = (uint32_t)(i >> 5);
            uint32_t cb = (uint32_t)(i & 31) * 8;
            *(uint2*)(smem + SB_XH + swz(r, cb)) =
                make_uint2(pack16(xr[ii].x, xr[ii].y), pack16(xr[ii].z, xr[ii].w));
        }
        if (t + 1 < task1) {
            #pragma unroll
            for (int ii = 0; ii < 8; ++ii)
                xr[ii] = xall[(size_t)(t + 1) * 2048 + ii * 256 + tid];
        }
        __syncthreads();   // X ready; all warps past prior out phase

        if (b != bcur) {   // (re)load kv tile (hi only); visibility via next sync
            const float2* kv2 = reinterpret_cast<const float2*>(g_kv) + (size_t)b * 8192;
            for (int i = tid; i < 8192; i += 256) {
                uint32_t f  = (uint32_t)(i >> 6);
                uint32_t cb = (uint32_t)(i & 63) * 4;
                float2 a = kv2[i];
                *(uint32_t*)(smem + SB_KVH + swz(f, cb)) = pack16(a.x, a.y);
            }
            bcur = b;
        }

        // ---- q projection (1-pass), warp tile 32x32 ----
        float pa[2][4][4];
        #pragma unroll
        for (int mb = 0; mb < 2; ++mb)
            #pragma unroll
            for (int nb = 0; nb < 4; ++nb)
                pa[mb][nb][0] = pa[mb][nb][1] = pa[mb][nb][2] = pa[mb][nb][3] = 0.f;
        {
            const uint32_t arow0 = (uint32_t)(m0 + (lane & 15));
            const uint32_t aco   = (uint32_t)((lane >> 4) & 1) * 16;
            const uint32_t brl   = (uint32_t)(lane & 15);
            #pragma unroll
            for (int ks = 0; ks < 8; ++ks) {
                uint32_t ah[2][4];
                uint32_t acb = (uint32_t)ks * 32 + aco;
                ldsm4(sb + SB_XH + swz(arow0,      acb), ah[0]);
                ldsm4(sb + SB_XH + swz(arow0 + 16, acb), ah[1]);
                #pragma unroll
                for (int ng = 0; ng < 2; ++ng) {
                    uint32_t br  = (uint32_t)ks * 16 + brl;
                    uint32_t bcb = (uint32_t)(c0 + ng * 16) * 2 + aco;
                    uint32_t bh[4];
                    ldsm4t(sb + SB_WQH + swz(br, bcb), bh);
                    mma1(pa[0][2 * ng], pa[0][2 * ng + 1], ah[0], bh);
                    mma1(pa[1][2 * ng], pa[1][2 * ng + 1], ah[1], bh);
                }
            }
        }
        // ---- epilogue: q = exp(.+bq) -> hi only ----
        #pragma unroll
        for (int mb = 0; mb < 2; ++mb) {
            int r0 = m0 + mb * 16 + er;
            #pragma unroll
            for (int nb = 0; nb < 4; ++nb) {
                int col = c0 + nb * 8 + ec;
                float b0 = sbq[col], b1 = sbq[col + 1];
                *(uint32_t*)(smem + SB_QH + swz((uint32_t)r0, (uint32_t)col * 2)) =
                    pack16(fexp(pa[mb][nb][0] + b0), fexp(pa[mb][nb][1] + b1));
                *(uint32_t*)(smem + SB_QH + swz((uint32_t)(r0 + 8), (uint32_t)col * 2)) =
                    pack16(fexp(pa[mb][nb][2] + b0), fexp(pa[mb][nb][3] + b1));
            }
        }
        __syncthreads();   // Q (and any reloaded KV) ready

        // ---- out = q @ kv (1-pass), warp tile 32x32 ----
        float oa[2][4][4];
        #pragma unroll
        for (int mb = 0; mb < 2; ++mb)
            #pragma unroll
            for (int nb = 0; nb < 4; ++nb)
                oa[mb][nb][0] = oa[mb][nb][1] = oa[mb][nb][2] = oa[mb][nb][3] = 0.f;
        {
            const uint32_t arow0 = (uint32_t)(m0 + (lane & 15));
            const uint32_t aco   = (uint32_t)((lane >> 4) & 1) * 16;
            const uint32_t brl   = (uint32_t)(lane & 15);
            #pragma unroll
            for (int ks = 0; ks < 8; ++ks) {
                uint32_t ah[2][4];
                uint32_t acb = (uint32_t)ks * 32 + aco;
                ldsm4(sb + SB_QH + swz(arow0,      acb), ah[0]);
                ldsm4(sb + SB_QH + swz(arow0 + 16, acb), ah[1]);
                #pragma unroll
                for (int ng = 0; ng < 2; ++ng) {
                    uint32_t br  = (uint32_t)ks * 16 + brl;
                    uint32_t bcb = (uint32_t)(c0 + ng * 16) * 2 + aco;
                    uint32_t bh[4];
                    ldsm4t(sb + SB_KVH + swz(br, bcb), bh);
                    mma1(oa[0][2 * ng], oa[0][2 * ng + 1], ah[0], bh);
                    mma1(oa[1][2 * ng], oa[1][2 * ng + 1], ah[1], bh);
                }
            }
        }
        // store
        float* og = out + (size_t)t * 8192;
        #pragma unroll
        for (int mb = 0; mb < 2; ++mb) {
            int r0 = m0 + mb * 16 + er;
            #pragma unroll
            for (int nb = 0; nb < 4; ++nb) {
                int col = c0 + nb * 8 + ec;
                *(float2*)(og + (size_t)r0 * 128 + col)       = make_float2(oa[mb][nb][0], oa[mb][nb][1]);
                *(float2*)(og + (size_t)(r0 + 8) * 128 + col) = make_float2(oa[mb][nb][2], oa[mb][nb][3]);
            }
        }
    }
}

// ---------------------------------------------------------------------------
extern "C" void kernel_launch(void* const* d_in, const int* in_sizes, int n_in,
                              void* d_out, int out_size) {
    const float* x  = (const float*)d_in[0];
    const float* Wq = (const float*)d_in[1];
    const float* bq = (const float*)d_in[2];
    const float* Wk = (const float*)d_in[3];
    const float* bk = (const float*)d_in[4];
    const float* Wv = (const float*)d_in[5];
    const float* bv = (const float*)d_in[6];
    float* out = (float*)d_out;
    (void)in_sizes; (void)n_in; (void)out_size;

    cudaFuncSetAttribute(stageA, cudaFuncAttributeMaxDynamicSharedMemorySize, SA_SMEM);
    cudaFuncSetAttribute(stageB, cudaFuncAttributeMaxDynamicSharedMemorySize, SB_SMEM);

    zero_kv_kernel<<<256, 256>>>();
    stageA<<<GRIDA, 256, SA_SMEM>>>(x, Wk, bk, Wv, bv);
    stageB<<<GRIDB, 256, SB_SMEM>>>(x, Wq, bq, out);
}

// round 15
// speedup vs baseline: 1.0780x; 1.0780x over previous
#include <cuda_runtime.h>
#include <cuda_fp16.h>
#include <cstdint>

// ============================================================================
// LinearAttentionLayer B=16,N=8192,F=128,U=128 fp32.
// Round 15: retry stage-A 2 CTAs/SM with the register peak fixed.
// Round-14's fused K/V proj held kvacc(64)+ka(32)+va(32) live -> spilled at
// the 128-reg/thread budget. De-fuse: K proj -> epilogue (regs die), then
// V proj -> epilogue. Peak ~115 regs. X fragments LDSM'd twice (+3% port).
// Stage B unchanged (2 CTAs/SM, prefetch). All GEMMs 1-pass fp16.
// ============================================================================

namespace {
constexpr int Bb = 16, Nn = 8192;
constexpr int SUBT = 64;
constexpr int TASKS = Bb * (Nn / SUBT);   // 2048
constexpr int GRIDA = 296;                // 2 CTAs/SM
constexpr int GRIDB = 296;                // 2 CTAs/SM

// stage A smem (bytes): all hi-only
constexpr int SA_WKH = 0;            // 128x128 fp16 = 32768
constexpr int SA_WVH = 32768;
constexpr int SA_XH  = 65536;        // 64x128 fp16 = 16384
constexpr int SA_KH  = 81920;
constexpr int SA_VH  = 98304;
constexpr int SA_BK  = 114688, SA_BV = 115200;
constexpr int SA_SMEM = 115712;      // x2 = 231424 <= SM smem

// stage B smem
constexpr int SB_WQH = 0;
constexpr int SB_KVH = 32768;
constexpr int SB_XH  = 65536;
constexpr int SB_QH  = 81920;
constexpr int SB_BQ  = 98304;
constexpr int SB_SMEM = 98816;       // x2 = 197632
}

__device__ float g_kv[Bb * 128 * 128];

// ---------------------------------------------------------------------------
__device__ __forceinline__ uint32_t smem_u32(const void* p) {
    uint32_t a;
    asm("{ .reg .u64 t; cvta.to.shared.u64 t, %1; cvt.u32.u64 %0, t; }" : "=r"(a) : "l"(p));
    return a;
}
__device__ __forceinline__ uint32_t swz(uint32_t row, uint32_t cb) {
    return row * 256u + (cb & 0x80u) + ((cb & 0x7Fu) ^ ((row & 7u) << 4));
}
__device__ __forceinline__ void ldsm4(uint32_t a, uint32_t* r) {
    asm volatile("ldmatrix.sync.aligned.m8n8.x4.shared.b16 {%0,%1,%2,%3}, [%4];"
        : "=r"(r[0]), "=r"(r[1]), "=r"(r[2]), "=r"(r[3]) : "r"(a));
}
__device__ __forceinline__ void ldsm4t(uint32_t a, uint32_t* r) {
    asm volatile("ldmatrix.sync.aligned.m8n8.x4.trans.shared.b16 {%0,%1,%2,%3}, [%4];"
        : "=r"(r[0]), "=r"(r[1]), "=r"(r[2]), "=r"(r[3]) : "r"(a));
}
__device__ __forceinline__ void mma16816f(float* d, const uint32_t* a, const uint32_t* b) {
    asm volatile(
        "mma.sync.aligned.m16n8k16.row.col.f32.f16.f16.f32 "
        "{%0,%1,%2,%3}, {%4,%5,%6,%7}, {%8,%9}, {%0,%1,%2,%3};"
        : "+f"(d[0]), "+f"(d[1]), "+f"(d[2]), "+f"(d[3])
        : "r"(a[0]), "r"(a[1]), "r"(a[2]), "r"(a[3]), "r"(b[0]), "r"(b[1]));
}
// 1-pass 16x16
__device__ __forceinline__ void mma1(float* d0, float* d1,
    const uint32_t* ah, const uint32_t* bh) {
    mma16816f(d0, ah, bh); mma16816f(d1, ah, bh + 2);
}

__device__ __forceinline__ uint32_t pack16(float v0, float v1) {
    __half2 h = __floats2half2_rn(v0, v1);
    return *reinterpret_cast<uint32_t*>(&h);
}

__device__ __forceinline__ float fexp(float x) {
    float t = x * 1.4426950408889634f;
    float r = t + 12582912.0f;
    int   e = __float_as_int(r) - 0x4B400000;
    float y = (t - (r - 12582912.0f)) * 0.6931471805599453f;
    float p = 1.38888894e-3f;
    p = fmaf(p, y, 8.33333377e-3f);
    p = fmaf(p, y, 4.16666679e-2f);
    p = fmaf(p, y, 1.66666672e-1f);
    p = fmaf(p, y, 0.5f);
    p = fmaf(p, y, 1.0f);
    p = fmaf(p, y, 1.0f);
    return __int_as_float(__float_as_int(p) + (e << 23));
}

__global__ void zero_kv_kernel() {
    int i = blockIdx.x * blockDim.x + threadIdx.x;
    reinterpret_cast<float4*>(g_kv)[i] = make_float4(0.f, 0.f, 0.f, 0.f);
}

// direct gmem -> fp16 smem (2-CTA overlap hides latency; no reg staging)
__device__ __forceinline__ void load_x_direct(
    char* smem, int XHo, const float4* xsrc, int tid)
{
    #pragma unroll
    for (int ii = 0; ii < 8; ++ii) {
        int i = tid + ii * 256;
        uint32_t r  = (uint32_t)(i >> 5);
        uint32_t cb = (uint32_t)(i & 31) * 8;
        float4 v = xsrc[i];
        *(uint2*)(smem + XHo + swz(r, cb)) =
            make_uint2(pack16(v.x, v.y), pack16(v.z, v.w));
    }
}

// one 32x32 projection: acc = X @ W, then epilogue (+bias, optional exp) -> Out
__device__ __forceinline__ void proj32(
    char* smem, uint32_t sb, int XHo, int WHo, int OHo,
    const float* sbias, bool do_exp, int pm0, int pc0, int lane,
    int er, int ec)
{
    float pa[2][4][4];
    #pragma unroll
    for (int mb = 0; mb < 2; ++mb)
        #pragma unroll
        for (int nb = 0; nb < 4; ++nb)
            pa[mb][nb][0] = pa[mb][nb][1] = pa[mb][nb][2] = pa[mb][nb][3] = 0.f;

    const uint32_t arow0 = (uint32_t)(pm0 + (lane & 15));
    const uint32_t aco   = (uint32_t)((lane >> 4) & 1) * 16;
    const uint32_t brl   = (uint32_t)(lane & 15);
    #pragma unroll
    for (int ks = 0; ks < 8; ++ks) {
        uint32_t ah[2][4];
        uint32_t acb = (uint32_t)ks * 32 + aco;
        ldsm4(sb + XHo + swz(arow0,      acb), ah[0]);
        ldsm4(sb + XHo + swz(arow0 + 16, acb), ah[1]);
        #pragma unroll
        for (int ng = 0; ng < 2; ++ng) {
            uint32_t br  = (uint32_t)ks * 16 + brl;
            uint32_t bcb = (uint32_t)(pc0 + ng * 16) * 2 + aco;
            uint32_t bh[4];
            ldsm4t(sb + WHo + swz(br, bcb), bh);
            mma1(pa[0][2 * ng], pa[0][2 * ng + 1], ah[0], bh);
            mma1(pa[1][2 * ng], pa[1][2 * ng + 1], ah[1], bh);
        }
    }
    #pragma unroll
    for (int mb = 0; mb < 2; ++mb) {
        int r0 = pm0 + mb * 16 + er;
        #pragma unroll
        for (int nb = 0; nb < 4; ++nb) {
            int col = pc0 + nb * 8 + ec;
            float b0 = sbias[col], b1 = sbias[col + 1];
            float v00 = pa[mb][nb][0] + b0, v01 = pa[mb][nb][1] + b1;
            float v10 = pa[mb][nb][2] + b0, v11 = pa[mb][nb][3] + b1;
            if (do_exp) { v00 = fexp(v00); v01 = fexp(v01); v10 = fexp(v10); v11 = fexp(v11); }
            *(uint32_t*)(smem + OHo + swz((uint32_t)r0, (uint32_t)col * 2)) = pack16(v00, v01);
            *(uint32_t*)(smem + OHo + swz((uint32_t)(r0 + 8), (uint32_t)col * 2)) = pack16(v10, v11);
        }
    }
}

// ===========================================================================
// Stage A — 2 CTAs/SM, de-fused K then V projections (reg peak ~115)
// ===========================================================================
__global__ void __launch_bounds__(256, 2) stageA(
    const float* __restrict__ x,
    const float* __restrict__ Wk, const float* __restrict__ bk,
    const float* __restrict__ Wv, const float* __restrict__ bv)
{
    extern __shared__ char smem[];
    const uint32_t sb = smem_u32(smem);
    const int tid = threadIdx.x, warp = tid >> 5, lane = tid & 31;

    const int task0 = (int)((long)blockIdx.x * TASKS / GRIDA);
    const int task1 = (int)((long)(blockIdx.x + 1) * TASKS / GRIDA);

    // W (hi only) into swizzled smem
    {
        const float2* wk2 = reinterpret_cast<const float2*>(Wk);
        const float2* wv2 = reinterpret_cast<const float2*>(Wv);
        for (int i = tid; i < 8192; i += 256) {
            uint32_t f  = (uint32_t)(i >> 6);
            uint32_t cb = (uint32_t)(i & 63) * 4;
            float2 a = wk2[i];
            *(uint32_t*)(smem + SA_WKH + swz(f, cb)) = pack16(a.x, a.y);
            a = wv2[i];
            *(uint32_t*)(smem + SA_WVH + swz(f, cb)) = pack16(a.x, a.y);
        }
        if (tid < 128) {
            ((float*)(smem + SA_BK))[tid] = bk[tid];
            ((float*)(smem + SA_BV))[tid] = bv[tid];
        }
    }

    const int pm0 = (warp >> 2) * 32, pc0 = (warp & 3) * 32;
    const int u0  = (warp & 3) * 32,  w0  = (warp >> 2) * 64;
    const int er = lane >> 2, ec = 2 * (lane & 3);

    float kvacc[2][8][4];
    #pragma unroll
    for (int mb = 0; mb < 2; ++mb)
        #pragma unroll
        for (int nb = 0; nb < 8; ++nb)
            kvacc[mb][nb][0] = kvacc[mb][nb][1] = kvacc[mb][nb][2] = kvacc[mb][nb][3] = 0.f;

    const float4* xall = reinterpret_cast<const float4*>(x);

    int bcur = task0 >> 7;
    for (int t = task0; t < task1; ++t) {
        const int b = t >> 7;
        if (b != bcur) {
            float* kvb = g_kv + (size_t)bcur * 16384;
            #pragma unroll
            for (int mb = 0; mb < 2; ++mb) {
                int ur = u0 + mb * 16 + er;
                #pragma unroll
                for (int nb = 0; nb < 8; ++nb) {
                    int col = w0 + nb * 8 + ec;
                    atomicAdd(&kvb[ur * 128 + col],           kvacc[mb][nb][0]);
                    atomicAdd(&kvb[ur * 128 + col + 1],       kvacc[mb][nb][1]);
                    atomicAdd(&kvb[(ur + 8) * 128 + col],     kvacc[mb][nb][2]);
                    atomicAdd(&kvb[(ur + 8) * 128 + col + 1], kvacc[mb][nb][3]);
                    kvacc[mb][nb][0] = kvacc[mb][nb][1] = kvacc[mb][nb][2] = kvacc[mb][nb][3] = 0.f;
                }
            }
            bcur = b;
        }

        load_x_direct(smem, SA_XH, xall + (size_t)t * 2048, tid);
        __syncthreads();   // X ready; all warps done with prior kv phase

        // ---- K projection (regs die at epilogue), then V projection ----
        proj32(smem, sb, SA_XH, SA_WKH, SA_KH,
               (const float*)(smem + SA_BK), true,  pm0, pc0, lane, er, ec);
        proj32(smem, sb, SA_XH, SA_WVH, SA_VH,
               (const float*)(smem + SA_BV), false, pm0, pc0, lane, er, ec);
        __syncthreads();   // K/V ready

        // ---- kv += k^T v (1-pass), warp tile 32u x 64w ----
        {
            const uint32_t krl = (uint32_t)(((lane >> 4) & 1) * 8 + (lane & 7));
            const uint32_t vco = (uint32_t)((lane >> 4) & 1) * 16;
            #pragma unroll
            for (int ks = 0; ks < 4; ++ks) {
                uint32_t kah[2][4];
                uint32_t kr = (uint32_t)ks * 16 + krl;
                #pragma unroll
                for (int mb = 0; mb < 2; ++mb) {
                    uint32_t ucb = (uint32_t)(u0 + mb * 16 + ((lane >> 3) & 1) * 8) * 2;
                    ldsm4t(sb + SA_KH + swz(kr, ucb), kah[mb]);
                }
                #pragma unroll
                for (int ng = 0; ng < 4; ++ng) {
                    uint32_t vr  = (uint32_t)(ks * 16 + (lane & 15));
                    uint32_t vcb = (uint32_t)(w0 + ng * 16) * 2 + vco;
                    uint32_t bh[4];
                    ldsm4t(sb + SA_VH + swz(vr, vcb), bh);
                    mma1(kvacc[0][2 * ng], kvacc[0][2 * ng + 1], kah[0], bh);
                    mma1(kvacc[1][2 * ng], kvacc[1][2 * ng + 1], kah[1], bh);
                }
            }
        }
    }

    // final flush
    {
        float* kvb = g_kv + (size_t)bcur * 16384;
        #pragma unroll
        for (int mb = 0; mb < 2; ++mb) {
            int ur = u0 + mb * 16 + er;
            #pragma unroll
            for (int nb = 0; nb < 8; ++nb) {
                int col = w0 + nb * 8 + ec;
                atomicAdd(&kvb[ur * 128 + col],           kvacc[mb][nb][0]);
                atomicAdd(&kvb[ur * 128 + col + 1],       kvacc[mb][nb][1]);
                atomicAdd(&kvb[(ur + 8) * 128 + col],     kvacc[mb][nb][2]);
                atomicAdd(&kvb[(ur + 8) * 128 + col + 1], kvacc[mb][nb][3]);
            }
        }
    }
}

// ===========================================================================
// Stage B — 2 CTAs/SM (unchanged from round-13 champion)
// ===========================================================================
__global__ void __launch_bounds__(256, 2) stageB(
    const float* __restrict__ x,
    const float* __restrict__ Wq, const float* __restrict__ bq,
    float* __restrict__ out)
{
    extern __shared__ char smem[];
    const uint32_t sb = smem_u32(smem);
    const int tid = threadIdx.x, warp = tid >> 5, lane = tid & 31;

    const int task0 = (int)((long)blockIdx.x * TASKS / GRIDB);
    const int task1 = (int)((long)(blockIdx.x + 1) * TASKS / GRIDB);

    {
        const float2* wq2 = reinterpret_cast<const float2*>(Wq);
        for (int i = tid; i < 8192; i += 256) {
            uint32_t f  = (uint32_t)(i >> 6);
            uint32_t cb = (uint32_t)(i & 63) * 4;
            float2 a = wq2[i];
            *(uint32_t*)(smem + SB_WQH + swz(f, cb)) = pack16(a.x, a.y);
        }
        if (tid < 128)
            ((float*)(smem + SB_BQ))[tid] = bq[tid];
    }

    const int m0 = (warp >> 2) * 32, c0 = (warp & 3) * 32;
    const int er = lane >> 2, ec = 2 * (lane & 3);
    const float* sbq = (const float*)(smem + SB_BQ);
    const float4* xall = reinterpret_cast<const float4*>(x);

    float4 xr[8];
    #pragma unroll
    for (int ii = 0; ii < 8; ++ii)
        xr[ii] = xall[(size_t)task0 * 2048 + ii * 256 + tid];

    int bcur = -1;
    for (int t = task0; t < task1; ++t) {
        const int b = t >> 7;

        #pragma unroll
        for (int ii = 0; ii < 8; ++ii) {
            int i = tid + ii * 256;
            uint32_t r  = (uint32_t)(i >> 5);
            uint32_t cb = (uint32_t)(i & 31) * 8;
            *(uint2*)(smem + SB_XH + swz(r, cb)) =
                make_uint2(pack16(xr[ii].x, xr[ii].y), pack16(xr[ii].z, xr[ii].w));
        }
        if (t + 1 < task1) {
            #pragma unroll
            for (int ii = 0; ii < 8; ++ii)
                xr[ii] = xall[(size_t)(t + 1) * 2048 + ii * 256 + tid];
        }
        __syncthreads();   // X ready; all warps past prior out phase

        if (b != bcur) {   // (re)load kv tile (hi only); visibility via next sync
            const float2* kv2 = reinterpret_cast<const float2*>(g_kv) + (size_t)b * 8192;
            for (int i = tid; i < 8192; i += 256) {
                uint32_t f  = (uint32_t)(i >> 6);
                uint32_t cb = (uint32_t)(i & 63) * 4;
                float2 a = kv2[i];
                *(uint32_t*)(smem + SB_KVH + swz(f, cb)) = pack16(a.x, a.y);
            }
            bcur = b;
        }

        // ---- q projection (1-pass), warp tile 32x32 ----
        float pa[2][4][4];
        #pragma unroll
        for (int mb = 0; mb < 2; ++mb)
            #pragma unroll
            for (int nb = 0; nb < 4; ++nb)
                pa[mb][nb][0] = pa[mb][nb][1] = pa[mb][nb][2] = pa[mb][nb][3] = 0.f;
        {
            const uint32_t arow0 = (uint32_t)(m0 + (lane & 15));
            const uint32_t aco   = (uint32_t)((lane >> 4) & 1) * 16;
            const uint32_t brl   = (uint32_t)(lane & 15);
            #pragma unroll
            for (int ks = 0; ks < 8; ++ks) {
                uint32_t ah[2][4];
                uint32_t acb = (uint32_t)ks * 32 + aco;
                ldsm4(sb + SB_XH + swz(arow0,      acb), ah[0]);
                ldsm4(sb + SB_XH + swz(arow0 + 16, acb), ah[1]);
                #pragma unroll
                for (int ng = 0; ng < 2; ++ng) {
                    uint32_t br  = (uint32_t)ks * 16 + brl;
                    uint32_t bcb = (uint32_t)(c0 + ng * 16) * 2 + aco;
                    uint32_t bh[4];
                    ldsm4t(sb + SB_WQH + swz(br, bcb), bh);
                    mma1(pa[0][2 * ng], pa[0][2 * ng + 1], ah[0], bh);
                    mma1(pa[1][2 * ng], pa[1][2 * ng + 1], ah[1], bh);
                }
            }
        }
        // ---- epilogue: q = exp(.+bq) -> hi only ----
        #pragma unroll
        for (int mb = 0; mb < 2; ++mb) {
            int r0 = m0 + mb * 16 + er;
            #pragma unroll
            for (int nb = 0; nb < 4; ++nb) {
                int col = c0 + nb * 8 + ec;
                float b0 = sbq[col], b1 = sbq[col + 1];
                *(uint32_t*)(smem + SB_QH + swz((uint32_t)r0, (uint32_t)col * 2)) =
                    pack16(fexp(pa[mb][nb][0] + b0), fexp(pa[mb][nb][1] + b1));
                *(uint32_t*)(smem + SB_QH + swz((uint32_t)(r0 + 8), (uint32_t)col * 2)) =
                    pack16(fexp(pa[mb][nb][2] + b0), fexp(pa[mb][nb][3] + b1));
            }
        }
        __syncthreads();   // Q (and any reloaded KV) ready

        // ---- out = q @ kv (1-pass), warp tile 32x32 ----
        float oa[2][4][4];
        #pragma unroll
        for (int mb = 0; mb < 2; ++mb)
            #pragma unroll
            for (int nb = 0; nb < 4; ++nb)
                oa[mb][nb][0] = oa[mb][nb][1] = oa[mb][nb][2] = oa[mb][nb][3] = 0.f;
        {
            const uint32_t arow0 = (uint32_t)(m0 + (lane & 15));
            const uint32_t aco   = (uint32_t)((lane >> 4) & 1) * 16;
            const uint32_t brl   = (uint32_t)(lane & 15);
            #pragma unroll
            for (int ks = 0; ks < 8; ++ks) {
                uint32_t ah[2][4];
                uint32_t acb = (uint32_t)ks * 32 + aco;
                ldsm4(sb + SB_QH + swz(arow0,      acb), ah[0]);
                ldsm4(sb + SB_QH + swz(arow0 + 16, acb), ah[1]);
                #pragma unroll
                for (int ng = 0; ng < 2; ++ng) {
                    uint32_t br  = (uint32_t)ks * 16 + brl;
                    uint32_t bcb = (uint32_t)(c0 + ng * 16) * 2 + aco;
                    uint32_t bh[4];
                    ldsm4t(sb + SB_KVH + swz(br, bcb), bh);
                    mma1(oa[0][2 * ng], oa[0][2 * ng + 1], ah[0], bh);
                    mma1(oa[1][2 * ng], oa[1][2 * ng + 1], ah[1], bh);
                }
            }
        }
        // store
        float* og = out + (size_t)t * 8192;
        #pragma unroll
        for (int mb = 0; mb < 2; ++mb) {
            int r0 = m0 + mb * 16 + er;
            #pragma unroll
            for (int nb = 0; nb < 4; ++nb) {
                int col = c0 + nb * 8 + ec;
                *(float2*)(og + (size_t)r0 * 128 + col)       = make_float2(oa[mb][nb][0], oa[mb][nb][1]);
                *(float2*)(og + (size_t)(r0 + 8) * 128 + col) = make_float2(oa[mb][nb][2], oa[mb][nb][3]);
            }
        }
    }
}

// ---------------------------------------------------------------------------
extern "C" void kernel_launch(void* const* d_in, const int* in_sizes, int n_in,
                              void* d_out, int out_size) {
    const float* x  = (const float*)d_in[0];
    const float* Wq = (const float*)d_in[1];
    const float* bq = (const float*)d_in[2];
    const float* Wk = (const float*)d_in[3];
    const float* bk = (const float*)d_in[4];
    const float* Wv = (const float*)d_in[5];
    const float* bv = (const float*)d_in[6];
    float* out = (float*)d_out;
    (void)in_sizes; (void)n_in; (void)out_size;

    cudaFuncSetAttribute(stageA, cudaFuncAttributeMaxDynamicSharedMemorySize, SA_SMEM);
    cudaFuncSetAttribute(stageB, cudaFuncAttributeMaxDynamicSharedMemorySize, SB_SMEM);

    zero_kv_kernel<<<256, 256>>>();
    stageA<<<GRIDA, 256, SA_SMEM>>>(x, Wk, bk, Wv, bv);
    stageB<<<GRIDB, 256, SB_SMEM>>>(x, Wq, bq, out);
}

// round 16
// speedup vs baseline: 1.1647x; 1.0804x over previous
#include <cuda_runtime.h>
#include <cuda_fp16.h>
#include <cstdint>

// ============================================================================
// LinearAttentionLayer B=16,N=8192,F=128,U=128 fp32.
// Round 16: stage A = round-13 champion config (1 CTA/SM, fused K/V proj,
// register prefetch) + X/K/V DOUBLE BUFFERING -> ONE __syncthreads per
// subtile (was two). Ordering: proj(i) X[p]->KV[p]; store X(i+1)->X[1-p];
// SYNC; kv(i) KV[p]. All other hazards span parity buffers across syncs.
// Stage B = round-13 exactly (2 CTAs/SM, prefetch). All GEMMs 1-pass fp16.
// ============================================================================

namespace {
constexpr int Bb = 16, Nn = 8192;
constexpr int SUBT = 64;
constexpr int TASKS = Bb * (Nn / SUBT);   // 2048
constexpr int GRIDA = 148;
constexpr int GRIDB = 296;                // 2 CTAs/SM

// stage A smem (bytes): W hi + double-buffered X/K/V + biases
constexpr int SA_WKH = 0;                 // 128x128 fp16 = 32768
constexpr int SA_WVH = 32768;
constexpr int SA_X0  = 65536;             // 2 x 16384
constexpr int SA_K0  = 98304;             // 2 x 16384
constexpr int SA_V0  = 131072;            // 2 x 16384
constexpr int SA_BK  = 163840, SA_BV = 164352;
constexpr int SA_SMEM = 164864;           // 1 CTA/SM

// stage B smem
constexpr int SB_WQH = 0;
constexpr int SB_KVH = 32768;
constexpr int SB_XH  = 65536;
constexpr int SB_QH  = 81920;
constexpr int SB_BQ  = 98304;
constexpr int SB_SMEM = 98816;            // x2 = 197632, 2 CTAs/SM
}

__device__ float g_kv[Bb * 128 * 128];

// ---------------------------------------------------------------------------
__device__ __forceinline__ uint32_t smem_u32(const void* p) {
    uint32_t a;
    asm("{ .reg .u64 t; cvta.to.shared.u64 t, %1; cvt.u32.u64 %0, t; }" : "=r"(a) : "l"(p));
    return a;
}
__device__ __forceinline__ uint32_t swz(uint32_t row, uint32_t cb) {
    return row * 256u + (cb & 0x80u) + ((cb & 0x7Fu) ^ ((row & 7u) << 4));
}
__device__ __forceinline__ void ldsm4(uint32_t a, uint32_t* r) {
    asm volatile("ldmatrix.sync.aligned.m8n8.x4.shared.b16 {%0,%1,%2,%3}, [%4];"
        : "=r"(r[0]), "=r"(r[1]), "=r"(r[2]), "=r"(r[3]) : "r"(a));
}
__device__ __forceinline__ void ldsm4t(uint32_t a, uint32_t* r) {
    asm volatile("ldmatrix.sync.aligned.m8n8.x4.trans.shared.b16 {%0,%1,%2,%3}, [%4];"
        : "=r"(r[0]), "=r"(r[1]), "=r"(r[2]), "=r"(r[3]) : "r"(a));
}
__device__ __forceinline__ void mma16816f(float* d, const uint32_t* a, const uint32_t* b) {
    asm volatile(
        "mma.sync.aligned.m16n8k16.row.col.f32.f16.f16.f32 "
        "{%0,%1,%2,%3}, {%4,%5,%6,%7}, {%8,%9}, {%0,%1,%2,%3};"
        : "+f"(d[0]), "+f"(d[1]), "+f"(d[2]), "+f"(d[3])
        : "r"(a[0]), "r"(a[1]), "r"(a[2]), "r"(a[3]), "r"(b[0]), "r"(b[1]));
}
__device__ __forceinline__ void mma1(float* d0, float* d1,
    const uint32_t* ah, const uint32_t* bh) {
    mma16816f(d0, ah, bh); mma16816f(d1, ah, bh + 2);
}

__device__ __forceinline__ uint32_t pack16(float v0, float v1) {
    __half2 h = __floats2half2_rn(v0, v1);
    return *reinterpret_cast<uint32_t*>(&h);
}

__device__ __forceinline__ float fexp(float x) {
    float t = x * 1.4426950408889634f;
    float r = t + 12582912.0f;
    int   e = __float_as_int(r) - 0x4B400000;
    float y = (t - (r - 12582912.0f)) * 0.6931471805599453f;
    float p = 1.38888894e-3f;
    p = fmaf(p, y, 8.33333377e-3f);
    p = fmaf(p, y, 4.16666679e-2f);
    p = fmaf(p, y, 1.66666672e-1f);
    p = fmaf(p, y, 0.5f);
    p = fmaf(p, y, 1.0f);
    p = fmaf(p, y, 1.0f);
    return __int_as_float(__float_as_int(p) + (e << 23));
}

__global__ void zero_kv_kernel() {
    int i = blockIdx.x * blockDim.x + threadIdx.x;
    reinterpret_cast<float4*>(g_kv)[i] = make_float4(0.f, 0.f, 0.f, 0.f);
}

// prefetched x regs (64x128 fp32 tile) -> fp16 hi swizzled smem
__device__ __forceinline__ void store_x_regs(
    char* smem, int XHo, const float4* xr, int tid)
{
    #pragma unroll
    for (int ii = 0; ii < 8; ++ii) {
        int i = tid + ii * 256;
        uint32_t r  = (uint32_t)(i >> 5);
        uint32_t cb = (uint32_t)(i & 31) * 8;
        float4 v = xr[ii];
        *(uint2*)(smem + XHo + swz(r, cb)) =
            make_uint2(pack16(v.x, v.y), pack16(v.z, v.w));
    }
}

// ===========================================================================
// Stage A — 1 CTA/SM, double-buffered X/K/V, ONE sync per subtile
// ===========================================================================
__global__ void __launch_bounds__(256, 1) stageA(
    const float* __restrict__ x,
    const float* __restrict__ Wk, const float* __restrict__ bk,
    const float* __restrict__ Wv, const float* __restrict__ bv)
{
    extern __shared__ char smem[];
    const uint32_t sb = smem_u32(smem);
    const int tid = threadIdx.x, warp = tid >> 5, lane = tid & 31;

    const int task0 = (int)((long)blockIdx.x * TASKS / GRIDA);
    const int task1 = (int)((long)(blockIdx.x + 1) * TASKS / GRIDA);

    // W (hi only) into swizzled smem
    {
        const float2* wk2 = reinterpret_cast<const float2*>(Wk);
        const float2* wv2 = reinterpret_cast<const float2*>(Wv);
        for (int i = tid; i < 8192; i += 256) {
            uint32_t f  = (uint32_t)(i >> 6);
            uint32_t cb = (uint32_t)(i & 63) * 4;
            float2 a = wk2[i];
            *(uint32_t*)(smem + SA_WKH + swz(f, cb)) = pack16(a.x, a.y);
            a = wv2[i];
            *(uint32_t*)(smem + SA_WVH + swz(f, cb)) = pack16(a.x, a.y);
        }
        if (tid < 128) {
            ((float*)(smem + SA_BK))[tid] = bk[tid];
            ((float*)(smem + SA_BV))[tid] = bv[tid];
        }
    }

    const int pm0 = (warp >> 2) * 32, pc0 = (warp & 3) * 32;
    const int u0  = (warp & 3) * 32,  w0  = (warp >> 2) * 64;
    const int er = lane >> 2, ec = 2 * (lane & 3);

    float kvacc[2][8][4];
    #pragma unroll
    for (int mb = 0; mb < 2; ++mb)
        #pragma unroll
        for (int nb = 0; nb < 8; ++nb)
            kvacc[mb][nb][0] = kvacc[mb][nb][1] = kvacc[mb][nb][2] = kvacc[mb][nb][3] = 0.f;

    const float* sbk = (const float*)(smem + SA_BK);
    const float* sbv = (const float*)(smem + SA_BV);
    const float4* xall = reinterpret_cast<const float4*>(x);

    // prologue: prefetch + store X for task0, prefetch task0+1, sync
    float4 xr[8];
    #pragma unroll
    for (int ii = 0; ii < 8; ++ii)
        xr[ii] = xall[(size_t)task0 * 2048 + ii * 256 + tid];
    store_x_regs(smem, SA_X0, xr, tid);   // parity 0
    if (task0 + 1 < task1) {
        #pragma unroll
        for (int ii = 0; ii < 8; ++ii)
            xr[ii] = xall[(size_t)(task0 + 1) * 2048 + ii * 256 + tid];
    }
    __syncthreads();   // X[0] visible (also covers W/bias loads)

    int p = 0;
    int bcur = task0 >> 7;
    for (int t = task0; t < task1; ++t) {
        const int b = t >> 7;
        if (b != bcur) {
            float* kvb = g_kv + (size_t)bcur * 16384;
            #pragma unroll
            for (int mb = 0; mb < 2; ++mb) {
                int ur = u0 + mb * 16 + er;
                #pragma unroll
                for (int nb = 0; nb < 8; ++nb) {
                    int col = w0 + nb * 8 + ec;
                    atomicAdd(&kvb[ur * 128 + col],           kvacc[mb][nb][0]);
                    atomicAdd(&kvb[ur * 128 + col + 1],       kvacc[mb][nb][1]);
                    atomicAdd(&kvb[(ur + 8) * 128 + col],     kvacc[mb][nb][2]);
                    atomicAdd(&kvb[(ur + 8) * 128 + col + 1], kvacc[mb][nb][3]);
                    kvacc[mb][nb][0] = kvacc[mb][nb][1] = kvacc[mb][nb][2] = kvacc[mb][nb][3] = 0.f;
                }
            }
            bcur = b;
        }

        const int XHo = SA_X0 + p * 16384;
        const int KHo = SA_K0 + p * 16384;
        const int VHo = SA_V0 + p * 16384;

        // ---- fused K/V projection (1-pass) from X[p], warp tile 32x32 ----
        float ka[2][4][4], va[2][4][4];
        #pragma unroll
        for (int mb = 0; mb < 2; ++mb)
            #pragma unroll
            for (int nb = 0; nb < 4; ++nb) {
                ka[mb][nb][0] = ka[mb][nb][1] = ka[mb][nb][2] = ka[mb][nb][3] = 0.f;
                va[mb][nb][0] = va[mb][nb][1] = va[mb][nb][2] = va[mb][nb][3] = 0.f;
            }
        {
            const uint32_t arow0 = (uint32_t)(pm0 + (lane & 15));
            const uint32_t aco   = (uint32_t)((lane >> 4) & 1) * 16;
            const uint32_t brl   = (uint32_t)(lane & 15);
            #pragma unroll
            for (int ks = 0; ks < 8; ++ks) {
                uint32_t ah[2][4];
                uint32_t acb = (uint32_t)ks * 32 + aco;
                ldsm4(sb + XHo + swz(arow0,      acb), ah[0]);
                ldsm4(sb + XHo + swz(arow0 + 16, acb), ah[1]);
                #pragma unroll
                for (int ng = 0; ng < 2; ++ng) {
                    uint32_t br  = (uint32_t)ks * 16 + brl;
                    uint32_t bcb = (uint32_t)(pc0 + ng * 16) * 2 + aco;
                    uint32_t bh[4];
                    ldsm4t(sb + SA_WKH + swz(br, bcb), bh);
                    mma1(ka[0][2 * ng], ka[0][2 * ng + 1], ah[0], bh);
                    mma1(ka[1][2 * ng], ka[1][2 * ng + 1], ah[1], bh);
                    ldsm4t(sb + SA_WVH + swz(br, bcb), bh);
                    mma1(va[0][2 * ng], va[0][2 * ng + 1], ah[0], bh);
                    mma1(va[1][2 * ng], va[1][2 * ng + 1], ah[1], bh);
                }
            }
        }
        // ---- epilogue -> K[p], V[p] ----
        #pragma unroll
        for (int mb = 0; mb < 2; ++mb) {
            int r0 = pm0 + mb * 16 + er;
            #pragma unroll
            for (int nb = 0; nb < 4; ++nb) {
                int col = pc0 + nb * 8 + ec;
                float bk0 = sbk[col], bk1 = sbk[col + 1];
                float bv0 = sbv[col], bv1 = sbv[col + 1];
                *(uint32_t*)(smem + KHo + swz((uint32_t)r0, (uint32_t)col * 2)) =
                    pack16(fexp(ka[mb][nb][0] + bk0), fexp(ka[mb][nb][1] + bk1));
                *(uint32_t*)(smem + KHo + swz((uint32_t)(r0 + 8), (uint32_t)col * 2)) =
                    pack16(fexp(ka[mb][nb][2] + bk0), fexp(ka[mb][nb][3] + bk1));
                *(uint32_t*)(smem + VHo + swz((uint32_t)r0, (uint32_t)col * 2)) =
                    pack16(va[mb][nb][0] + bv0, va[mb][nb][1] + bv1);
                *(uint32_t*)(smem + VHo + swz((uint32_t)(r0 + 8), (uint32_t)col * 2)) =
                    pack16(va[mb][nb][2] + bv0, va[mb][nb][3] + bv1);
            }
        }

        // ---- store next X into X[1-p]; prefetch t+2 ----
        if (t + 1 < task1) {
            store_x_regs(smem, SA_X0 + (1 - p) * 16384, xr, tid);
            if (t + 2 < task1) {
                #pragma unroll
                for (int ii = 0; ii < 8; ++ii)
                    xr[ii] = xall[(size_t)(t + 2) * 2048 + ii * 256 + tid];
            }
        }

        __syncthreads();   // K/V[p] ready; X[1-p] ready for next proj

        // ---- kv += k^T v from K/V[p], warp tile 32u x 64w ----
        {
            const uint32_t krl = (uint32_t)(((lane >> 4) & 1) * 8 + (lane & 7));
            const uint32_t vco = (uint32_t)((lane >> 4) & 1) * 16;
            #pragma unroll
            for (int ks = 0; ks < 4; ++ks) {
                uint32_t kah[2][4];
                uint32_t kr = (uint32_t)ks * 16 + krl;
                #pragma unroll
                for (int mb = 0; mb < 2; ++mb) {
                    uint32_t ucb = (uint32_t)(u0 + mb * 16 + ((lane >> 3) & 1) * 8) * 2;
                    ldsm4t(sb + KHo + swz(kr, ucb), kah[mb]);
                }
                #pragma unroll
                for (int ng = 0; ng < 4; ++ng) {
                    uint32_t vr  = (uint32_t)(ks * 16 + (lane & 15));
                    uint32_t vcb = (uint32_t)(w0 + ng * 16) * 2 + vco;
                    uint32_t bh[4];
                    ldsm4t(sb + VHo + swz(vr, vcb), bh);
                    mma1(kvacc[0][2 * ng], kvacc[0][2 * ng + 1], kah[0], bh);
                    mma1(kvacc[1][2 * ng], kvacc[1][2 * ng + 1], kah[1], bh);
                }
            }
        }
        p ^= 1;
    }

    // final flush
    {
        float* kvb = g_kv + (size_t)bcur * 16384;
        #pragma unroll
        for (int mb = 0; mb < 2; ++mb) {
            int ur = u0 + mb * 16 + er;
            #pragma unroll
            for (int nb = 0; nb < 8; ++nb) {
                int col = w0 + nb * 8 + ec;
                atomicAdd(&kvb[ur * 128 + col],           kvacc[mb][nb][0]);
                atomicAdd(&kvb[ur * 128 + col + 1],       kvacc[mb][nb][1]);
                atomicAdd(&kvb[(ur + 8) * 128 + col],     kvacc[mb][nb][2]);
                atomicAdd(&kvb[(ur + 8) * 128 + col + 1], kvacc[mb][nb][3]);
            }
        }
    }
}

// ===========================================================================
// Stage B — 2 CTAs/SM (round-13 champion, unchanged)
// ===========================================================================
__global__ void __launch_bounds__(256, 2) stageB(
    const float* __restrict__ x,
    const float* __restrict__ Wq, const float* __restrict__ bq,
    float* __restrict__ out)
{
    extern __shared__ char smem[];
    const uint32_t sb = smem_u32(smem);
    const int tid = threadIdx.x, warp = tid >> 5, lane = tid & 31;

    const int task0 = (int)((long)blockIdx.x * TASKS / GRIDB);
    const int task1 = (int)((long)(blockIdx.x + 1) * TASKS / GRIDB);

    {
        const float2* wq2 = reinterpret_cast<const float2*>(Wq);
        for (int i = tid; i < 8192; i += 256) {
            uint32_t f  = (uint32_t)(i >> 6);
            uint32_t cb = (uint32_t)(i & 63) * 4;
            float2 a = wq2[i];
            *(uint32_t*)(smem + SB_WQH + swz(f, cb)) = pack16(a.x, a.y);
        }
        if (tid < 128)
            ((float*)(smem + SB_BQ))[tid] = bq[tid];
    }

    const int m0 = (warp >> 2) * 32, c0 = (warp & 3) * 32;
    const int er = lane >> 2, ec = 2 * (lane & 3);
    const float* sbq = (const float*)(smem + SB_BQ);
    const float4* xall = reinterpret_cast<const float4*>(x);

    float4 xr[8];
    #pragma unroll
    for (int ii = 0; ii < 8; ++ii)
        xr[ii] = xall[(size_t)task0 * 2048 + ii * 256 + tid];

    int bcur = -1;
    for (int t = task0; t < task1; ++t) {
        const int b = t >> 7;

        #pragma unroll
        for (int ii = 0; ii < 8; ++ii) {
            int i = tid + ii * 256;
            uint32_t r  = (uint32_t)(i >> 5);
            uint32_t cb = (uint32_t)(i & 31) * 8;
            *(uint2*)(smem + SB_XH + swz(r, cb)) =
                make_uint2(pack16(xr[ii].x, xr[ii].y), pack16(xr[ii].z, xr[ii].w));
        }
        if (t + 1 < task1) {
            #pragma unroll
            for (int ii = 0; ii < 8; ++ii)
                xr[ii] = xall[(size_t)(t + 1) * 2048 + ii * 256 + tid];
        }
        __syncthreads();   // X ready; all warps past prior out phase

        if (b != bcur) {   // (re)load kv tile (hi only); visibility via next sync
            const float2* kv2 = reinterpret_cast<const float2*>(g_kv) + (size_t)b * 8192;
            for (int i = tid; i < 8192; i += 256) {
                uint32_t f  = (uint32_t)(i >> 6);
                uint32_t cb = (uint32_t)(i & 63) * 4;
                float2 a = kv2[i];
                *(uint32_t*)(smem + SB_KVH + swz(f, cb)) = pack16(a.x, a.y);
            }
            bcur = b;
        }

        // ---- q projection (1-pass), warp tile 32x32 ----
        float pa[2][4][4];
        #pragma unroll
        for (int mb = 0; mb < 2; ++mb)
            #pragma unroll
            for (int nb = 0; nb < 4; ++nb)
                pa[mb][nb][0] = pa[mb][nb][1] = pa[mb][nb][2] = pa[mb][nb][3] = 0.f;
        {
            const uint32_t arow0 = (uint32_t)(m0 + (lane & 15));
            const uint32_t aco   = (uint32_t)((lane >> 4) & 1) * 16;
            const uint32_t brl   = (uint32_t)(lane & 15);
            #pragma unroll
            for (int ks = 0; ks < 8; ++ks) {
                uint32_t ah[2][4];
                uint32_t acb = (uint32_t)ks * 32 + aco;
                ldsm4(sb + SB_XH + swz(arow0,      acb), ah[0]);
                ldsm4(sb + SB_XH + swz(arow0 + 16, acb), ah[1]);
                #pragma unroll
                for (int ng = 0; ng < 2; ++ng) {
                    uint32_t br  = (uint32_t)ks * 16 + brl;
                    uint32_t bcb = (uint32_t)(c0 + ng * 16) * 2 + aco;
                    uint32_t bh[4];
                    ldsm4t(sb + SB_WQH + swz(br, bcb), bh);
                    mma1(pa[0][2 * ng], pa[0][2 * ng + 1], ah[0], bh);
                    mma1(pa[1][2 * ng], pa[1][2 * ng + 1], ah[1], bh);
                }
            }
        }
        // ---- epilogue: q = exp(.+bq) -> hi only ----
        #pragma unroll
        for (int mb = 0; mb < 2; ++mb) {
            int r0 = m0 + mb * 16 + er;
            #pragma unroll
            for (int nb = 0; nb < 4; ++nb) {
                int col = c0 + nb * 8 + ec;
                float b0 = sbq[col], b1 = sbq[col + 1];
                *(uint32_t*)(smem + SB_QH + swz((uint32_t)r0, (uint32_t)col * 2)) =
                    pack16(fexp(pa[mb][nb][0] + b0), fexp(pa[mb][nb][1] + b1));
                *(uint32_t*)(smem + SB_QH + swz((uint32_t)(r0 + 8), (uint32_t)col * 2)) =
                    pack16(fexp(pa[mb][nb][2] + b0), fexp(pa[mb][nb][3] + b1));
            }
        }
        __syncthreads();   // Q (and any reloaded KV) ready

        // ---- out = q @ kv (1-pass), warp tile 32x32 ----
        float oa[2][4][4];
        #pragma unroll
        for (int mb = 0; mb < 2; ++mb)
            #pragma unroll
            for (int nb = 0; nb < 4; ++nb)
                oa[mb][nb][0] = oa[mb][nb][1] = oa[mb][nb][2] = oa[mb][nb][3] = 0.f;
        {
            const uint32_t arow0 = (uint32_t)(m0 + (lane & 15));
            const uint32_t aco   = (uint32_t)((lane >> 4) & 1) * 16;
            const uint32_t brl   = (uint32_t)(lane & 15);
            #pragma unroll
            for (int ks = 0; ks < 8; ++ks) {
                uint32_t ah[2][4];
                uint32_t acb = (uint32_t)ks * 32 + aco;
                ldsm4(sb + SB_QH + swz(arow0,      acb), ah[0]);
                ldsm4(sb + SB_QH + swz(arow0 + 16, acb), ah[1]);
                #pragma unroll
                for (int ng = 0; ng < 2; ++ng) {
                    uint32_t br  = (uint32_t)ks * 16 + brl;
                    uint32_t bcb = (uint32_t)(c0 + ng * 16) * 2 + aco;
                    uint32_t bh[4];
                    ldsm4t(sb + SB_KVH + swz(br, bcb), bh);
                    mma1(oa[0][2 * ng], oa[0][2 * ng + 1], ah[0], bh);
                    mma1(oa[1][2 * ng], oa[1][2 * ng + 1], ah[1], bh);
                }
            }
        }
        // store
        float* og = out + (size_t)t * 8192;
        #pragma unroll
        for (int mb = 0; mb < 2; ++mb) {
            int r0 = m0 + mb * 16 + er;
            #pragma unroll
            for (int nb = 0; nb < 4; ++nb) {
                int col = c0 + nb * 8 + ec;
                *(float2*)(og + (size_t)r0 * 128 + col)       = make_float2(oa[mb][nb][0], oa[mb][nb][1]);
                *(float2*)(og + (size_t)(r0 + 8) * 128 + col) = make_float2(oa[mb][nb][2], oa[mb][nb][3]);
            }
        }
    }
}

// ---------------------------------------------------------------------------
extern "C" void kernel_launch(void* const* d_in, const int* in_sizes, int n_in,
                              void* d_out, int out_size) {
    const float* x  = (const float*)d_in[0];
    const float* Wq = (const float*)d_in[1];
    const float* bq = (const float*)d_in[2];
    const float* Wk = (const float*)d_in[3];
    const float* bk = (const float*)d_in[4];
    const float* Wv = (const float*)d_in[5];
    const float* bv = (const float*)d_in[6];
    float* out = (float*)d_out;
    (void)in_sizes; (void)n_in; (void)out_size;

    cudaFuncSetAttribute(stageA, cudaFuncAttributeMaxDynamicSharedMemorySize, SA_SMEM);
    cudaFuncSetAttribute(stageB, cudaFuncAttributeMaxDynamicSharedMemorySize, SB_SMEM);

    zero_kv_kernel<<<256, 256>>>();
    stageA<<<GRIDA, 256, SA_SMEM>>>(x, Wk, bk, Wv, bv);
    stageB<<<GRIDB, 256, SB_SMEM>>>(x, Wq, bq, out);
}

// round 17
// speedup vs baseline: 1.1934x; 1.0247x over previous
#include <cuda_runtime.h>
#include <cuda_fp16.h>
#include <cstdint>

// ============================================================================
// LinearAttentionLayer B=16,N=8192,F=128,U=128 fp32.
// Round 17: stage A = round-13 champion + write-through of swizzled fp16
// X tiles to g_xh scratch. Stage B: x front-end replaced by cp.async of the
// pre-swizzled fp16 tiles (identity copy, double-buffered), bq in registers
// -> ~32 regs freed under lb(256,2), half the x HBM, no convert work.
// All GEMMs 1-pass fp16 (storage roundings dominate error; numerics identical).
// ============================================================================

namespace {
constexpr int Bb = 16, Nn = 8192;
constexpr int SUBT = 64;
constexpr int TASKS = Bb * (Nn / SUBT);   // 2048
constexpr int GRIDA = 148;
constexpr int GRIDB = 296;                // 2 CTAs/SM

// stage A smem (bytes): all hi-only (round-13 layout)
constexpr int SA_WKH = 0;            // 128x128 fp16 = 32768
constexpr int SA_WVH = 32768;
constexpr int SA_XH  = 65536;        // 64x128 fp16 = 16384
constexpr int SA_KH  = 81920;
constexpr int SA_VH  = 98304;
constexpr int SA_BK  = 114688, SA_BV = 115200;
constexpr int SA_SMEM = 115712;

// stage B smem: WQ, KV, X double-buffered, Q. (bq lives in registers)
constexpr int SB_WQH = 0;
constexpr int SB_KVH = 32768;
constexpr int SB_X0  = 65536;        // 2 x 16384
constexpr int SB_QH  = 98304;
constexpr int SB_SMEM = 114688;      // x2 = 229376 (+reserve) fits 228KB SM
}

__device__ float g_kv[Bb * 128 * 128];
__device__ uint8_t g_xh[(size_t)TASKS * 16384];   // swizzled fp16 x tiles, 33.5MB

// ---------------------------------------------------------------------------
__device__ __forceinline__ uint32_t smem_u32(const void* p) {
    uint32_t a;
    asm("{ .reg .u64 t; cvta.to.shared.u64 t, %1; cvt.u32.u64 %0, t; }" : "=r"(a) : "l"(p));
    return a;
}
__device__ __forceinline__ uint32_t swz(uint32_t row, uint32_t cb) {
    return row * 256u + (cb & 0x80u) + ((cb & 0x7Fu) ^ ((row & 7u) << 4));
}
__device__ __forceinline__ void ldsm4(uint32_t a, uint32_t* r) {
    asm volatile("ldmatrix.sync.aligned.m8n8.x4.shared.b16 {%0,%1,%2,%3}, [%4];"
        : "=r"(r[0]), "=r"(r[1]), "=r"(r[2]), "=r"(r[3]) : "r"(a));
}
__device__ __forceinline__ void ldsm4t(uint32_t a, uint32_t* r) {
    asm volatile("ldmatrix.sync.aligned.m8n8.x4.trans.shared.b16 {%0,%1,%2,%3}, [%4];"
        : "=r"(r[0]), "=r"(r[1]), "=r"(r[2]), "=r"(r[3]) : "r"(a));
}
__device__ __forceinline__ void mma16816f(float* d, const uint32_t* a, const uint32_t* b) {
    asm volatile(
        "mma.sync.aligned.m16n8k16.row.col.f32.f16.f16.f32 "
        "{%0,%1,%2,%3}, {%4,%5,%6,%7}, {%8,%9}, {%0,%1,%2,%3};"
        : "+f"(d[0]), "+f"(d[1]), "+f"(d[2]), "+f"(d[3])
        : "r"(a[0]), "r"(a[1]), "r"(a[2]), "r"(a[3]), "r"(b[0]), "r"(b[1]));
}
__device__ __forceinline__ void mma1(float* d0, float* d1,
    const uint32_t* ah, const uint32_t* bh) {
    mma16816f(d0, ah, bh); mma16816f(d1, ah, bh + 2);
}

__device__ __forceinline__ uint32_t pack16(float v0, float v1) {
    __half2 h = __floats2half2_rn(v0, v1);
    return *reinterpret_cast<uint32_t*>(&h);
}
__device__ __forceinline__ void cp16(uint32_t saddr, const void* g) {
    asm volatile("cp.async.ca.shared.global [%0], [%1], 16;" :: "r"(saddr), "l"(g));
}
#define CP_COMMIT() asm volatile("cp.async.commit_group;" ::: "memory")
#define CP_WAIT1()  asm volatile("cp.async.wait_group 1;" ::: "memory")

__device__ __forceinline__ float fexp(float x) {
    float t = x * 1.4426950408889634f;
    float r = t + 12582912.0f;
    int   e = __float_as_int(r) - 0x4B400000;
    float y = (t - (r - 12582912.0f)) * 0.6931471805599453f;
    float p = 1.38888894e-3f;
    p = fmaf(p, y, 8.33333377e-3f);
    p = fmaf(p, y, 4.16666679e-2f);
    p = fmaf(p, y, 1.66666672e-1f);
    p = fmaf(p, y, 0.5f);
    p = fmaf(p, y, 1.0f);
    p = fmaf(p, y, 1.0f);
    return __int_as_float(__float_as_int(p) + (e << 23));
}

__global__ void zero_kv_kernel() {
    int i = blockIdx.x * blockDim.x + threadIdx.x;
    reinterpret_cast<float4*>(g_kv)[i] = make_float4(0.f, 0.f, 0.f, 0.f);
}

// prefetched x regs -> fp16 hi swizzled smem + write-through to g_xh tile
__device__ __forceinline__ void store_x_regs_wt(
    char* smem, int XHo, uint8_t* gtile, const float4* xr, int tid)
{
    #pragma unroll
    for (int ii = 0; ii < 8; ++ii) {
        int i = tid + ii * 256;
        uint32_t r  = (uint32_t)(i >> 5);
        uint32_t cb = (uint32_t)(i & 31) * 8;
        float4 v = xr[ii];
        uint2 pk = make_uint2(pack16(v.x, v.y), pack16(v.z, v.w));
        uint32_t o = swz(r, cb);
        *(uint2*)(smem + XHo + o) = pk;
        *(uint2*)(gtile + o) = pk;           // write-through (async drain)
    }
}

// ===========================================================================
// Stage A — round-13 champion + write-through
// ===========================================================================
__global__ void __launch_bounds__(256, 1) stageA(
    const float* __restrict__ x,
    const float* __restrict__ Wk, const float* __restrict__ bk,
    const float* __restrict__ Wv, const float* __restrict__ bv)
{
    extern __shared__ char smem[];
    const uint32_t sb = smem_u32(smem);
    const int tid = threadIdx.x, warp = tid >> 5, lane = tid & 31;

    const int task0 = (int)((long)blockIdx.x * TASKS / GRIDA);
    const int task1 = (int)((long)(blockIdx.x + 1) * TASKS / GRIDA);

    {
        const float2* wk2 = reinterpret_cast<const float2*>(Wk);
        const float2* wv2 = reinterpret_cast<const float2*>(Wv);
        for (int i = tid; i < 8192; i += 256) {
            uint32_t f  = (uint32_t)(i >> 6);
            uint32_t cb = (uint32_t)(i & 63) * 4;
            float2 a = wk2[i];
            *(uint32_t*)(smem + SA_WKH + swz(f, cb)) = pack16(a.x, a.y);
            a = wv2[i];
            *(uint32_t*)(smem + SA_WVH + swz(f, cb)) = pack16(a.x, a.y);
        }
        if (tid < 128) {
            ((float*)(smem + SA_BK))[tid] = bk[tid];
            ((float*)(smem + SA_BV))[tid] = bv[tid];
        }
    }

    const int pm0 = (warp >> 2) * 32, pc0 = (warp & 3) * 32;
    const int u0  = (warp & 3) * 32,  w0  = (warp >> 2) * 64;
    const int er = lane >> 2, ec = 2 * (lane & 3);

    float kvacc[2][8][4];
    #pragma unroll
    for (int mb = 0; mb < 2; ++mb)
        #pragma unroll
        for (int nb = 0; nb < 8; ++nb)
            kvacc[mb][nb][0] = kvacc[mb][nb][1] = kvacc[mb][nb][2] = kvacc[mb][nb][3] = 0.f;

    const float* sbk = (const float*)(smem + SA_BK);
    const float* sbv = (const float*)(smem + SA_BV);
    const float4* xall = reinterpret_cast<const float4*>(x);

    float4 xr[8];
    #pragma unroll
    for (int ii = 0; ii < 8; ++ii)
        xr[ii] = xall[(size_t)task0 * 2048 + ii * 256 + tid];

    int bcur = task0 >> 7;
    for (int t = task0; t < task1; ++t) {
        const int b = t >> 7;
        if (b != bcur) {
            float* kvb = g_kv + (size_t)bcur * 16384;
            #pragma unroll
            for (int mb = 0; mb < 2; ++mb) {
                int ur = u0 + mb * 16 + er;
                #pragma unroll
                for (int nb = 0; nb < 8; ++nb) {
                    int col = w0 + nb * 8 + ec;
                    atomicAdd(&kvb[ur * 128 + col],           kvacc[mb][nb][0]);
                    atomicAdd(&kvb[ur * 128 + col + 1],       kvacc[mb][nb][1]);
                    atomicAdd(&kvb[(ur + 8) * 128 + col],     kvacc[mb][nb][2]);
                    atomicAdd(&kvb[(ur + 8) * 128 + col + 1], kvacc[mb][nb][3]);
                    kvacc[mb][nb][0] = kvacc[mb][nb][1] = kvacc[mb][nb][2] = kvacc[mb][nb][3] = 0.f;
                }
            }
            bcur = b;
        }

        store_x_regs_wt(smem, SA_XH, g_xh + (size_t)t * 16384, xr, tid);
        if (t + 1 < task1) {
            #pragma unroll
            for (int ii = 0; ii < 8; ++ii)
                xr[ii] = xall[(size_t)(t + 1) * 2048 + ii * 256 + tid];
        }
        __syncthreads();   // X ready; all warps done with prior kv phase

        // ---- fused K/V projection (1-pass), warp tile 32x32 ----
        float ka[2][4][4], va[2][4][4];
        #pragma unroll
        for (int mb = 0; mb < 2; ++mb)
            #pragma unroll
            for (int nb = 0; nb < 4; ++nb) {
                ka[mb][nb][0] = ka[mb][nb][1] = ka[mb][nb][2] = ka[mb][nb][3] = 0.f;
                va[mb][nb][0] = va[mb][nb][1] = va[mb][nb][2] = va[mb][nb][3] = 0.f;
            }
        {
            const uint32_t arow0 = (uint32_t)(pm0 + (lane & 15));
            const uint32_t aco   = (uint32_t)((lane >> 4) & 1) * 16;
            const uint32_t brl   = (uint32_t)(lane & 15);
            #pragma unroll
            for (int ks = 0; ks < 8; ++ks) {
                uint32_t ah[2][4];
                uint32_t acb = (uint32_t)ks * 32 + aco;
                ldsm4(sb + SA_XH + swz(arow0,      acb), ah[0]);
                ldsm4(sb + SA_XH + swz(arow0 + 16, acb), ah[1]);
                #pragma unroll
                for (int ng = 0; ng < 2; ++ng) {
                    uint32_t br  = (uint32_t)ks * 16 + brl;
                    uint32_t bcb = (uint32_t)(pc0 + ng * 16) * 2 + aco;
                    uint32_t bh[4];
                    ldsm4t(sb + SA_WKH + swz(br, bcb), bh);
                    mma1(ka[0][2 * ng], ka[0][2 * ng + 1], ah[0], bh);
                    mma1(ka[1][2 * ng], ka[1][2 * ng + 1], ah[1], bh);
                    ldsm4t(sb + SA_WVH + swz(br, bcb), bh);
                    mma1(va[0][2 * ng], va[0][2 * ng + 1], ah[0], bh);
                    mma1(va[1][2 * ng], va[1][2 * ng + 1], ah[1], bh);
                }
            }
        }
        // ---- epilogue ----
        #pragma unroll
        for (int mb = 0; mb < 2; ++mb) {
            int r0 = pm0 + mb * 16 + er;
            #pragma unroll
            for (int nb = 0; nb < 4; ++nb) {
                int col = pc0 + nb * 8 + ec;
                float bk0 = sbk[col], bk1 = sbk[col + 1];
                float bv0 = sbv[col], bv1 = sbv[col + 1];
                *(uint32_t*)(smem + SA_KH + swz((uint32_t)r0, (uint32_t)col * 2)) =
                    pack16(fexp(ka[mb][nb][0] + bk0), fexp(ka[mb][nb][1] + bk1));
                *(uint32_t*)(smem + SA_KH + swz((uint32_t)(r0 + 8), (uint32_t)col * 2)) =
                    pack16(fexp(ka[mb][nb][2] + bk0), fexp(ka[mb][nb][3] + bk1));
                *(uint32_t*)(smem + SA_VH + swz((uint32_t)r0, (uint32_t)col * 2)) =
                    pack16(va[mb][nb][0] + bv0, va[mb][nb][1] + bv1);
                *(uint32_t*)(smem + SA_VH + swz((uint32_t)(r0 + 8), (uint32_t)col * 2)) =
                    pack16(va[mb][nb][2] + bv0, va[mb][nb][3] + bv1);
            }
        }
        __syncthreads();   // K/V ready

        // ---- kv += k^T v (1-pass), warp tile 32u x 64w ----
        {
            const uint32_t krl = (uint32_t)(((lane >> 4) & 1) * 8 + (lane & 7));
            const uint32_t vco = (uint32_t)((lane >> 4) & 1) * 16;
            #pragma unroll
            for (int ks = 0; ks < 4; ++ks) {
                uint32_t kah[2][4];
                uint32_t kr = (uint32_t)ks * 16 + krl;
                #pragma unroll
                for (int mb = 0; mb < 2; ++mb) {
                    uint32_t ucb = (uint32_t)(u0 + mb * 16 + ((lane >> 3) & 1) * 8) * 2;
                    ldsm4t(sb + SA_KH + swz(kr, ucb), kah[mb]);
                }
                #pragma unroll
                for (int ng = 0; ng < 4; ++ng) {
                    uint32_t vr  = (uint32_t)(ks * 16 + (lane & 15));
                    uint32_t vcb = (uint32_t)(w0 + ng * 16) * 2 + vco;
                    uint32_t bh[4];
                    ldsm4t(sb + SA_VH + swz(vr, vcb), bh);
                    mma1(kvacc[0][2 * ng], kvacc[0][2 * ng + 1], kah[0], bh);
                    mma1(kvacc[1][2 * ng], kvacc[1][2 * ng + 1], kah[1], bh);
                }
            }
        }
    }

    // final flush
    {
        float* kvb = g_kv + (size_t)bcur * 16384;
        #pragma unroll
        for (int mb = 0; mb < 2; ++mb) {
            int ur = u0 + mb * 16 + er;
            #pragma unroll
            for (int nb = 0; nb < 8; ++nb) {
                int col = w0 + nb * 8 + ec;
                atomicAdd(&kvb[ur * 128 + col],           kvacc[mb][nb][0]);
                atomicAdd(&kvb[ur * 128 + col + 1],       kvacc[mb][nb][1]);
                atomicAdd(&kvb[(ur + 8) * 128 + col],     kvacc[mb][nb][2]);
                atomicAdd(&kvb[(ur + 8) * 128 + col + 1], kvacc[mb][nb][3]);
            }
        }
    }
}

// ===========================================================================
// Stage B — 2 CTAs/SM, cp.async double-buffered X from g_xh, bq in regs
// ===========================================================================
__global__ void __launch_bounds__(256, 2) stageB(
    const float* __restrict__ x,
    const float* __restrict__ Wq, const float* __restrict__ bq,
    float* __restrict__ out)
{
    extern __shared__ char smem[];
    const uint32_t sb = smem_u32(smem);
    const int tid = threadIdx.x, warp = tid >> 5, lane = tid & 31;

    const int task0 = (int)((long)blockIdx.x * TASKS / GRIDB);
    const int task1 = (int)((long)(blockIdx.x + 1) * TASKS / GRIDB);

    {
        const float2* wq2 = reinterpret_cast<const float2*>(Wq);
        for (int i = tid; i < 8192; i += 256) {
            uint32_t f  = (uint32_t)(i >> 6);
            uint32_t cb = (uint32_t)(i & 63) * 4;
            float2 a = wq2[i];
            *(uint32_t*)(smem + SB_WQH + swz(f, cb)) = pack16(a.x, a.y);
        }
    }

    const int m0 = (warp >> 2) * 32, c0 = (warp & 3) * 32;
    const int er = lane >> 2, ec = 2 * (lane & 3);

    // bq for this thread's epilogue columns (8 regs)
    float bqr[8];
    #pragma unroll
    for (int nb = 0; nb < 4; ++nb) {
        bqr[2 * nb]     = bq[c0 + nb * 8 + ec];
        bqr[2 * nb + 1] = bq[c0 + nb * 8 + ec + 1];
    }
    (void)x;

    // prologue: async-load X[0] <- xh(task0)
    {
        const uint8_t* gt = g_xh + (size_t)task0 * 16384;
        #pragma unroll
        for (int ii = 0; ii < 4; ++ii)
            cp16(sb + SB_X0 + tid * 16 + ii * 4096, gt + tid * 16 + ii * 4096);
        CP_COMMIT();
    }

    int p = 0;
    int bcur = -1;
    for (int t = task0; t < task1; ++t) {
        const int b = t >> 7;

        // issue next tile into X[1-p] (clamped; last iter re-copies harmlessly)
        {
            int tn = (t + 1 < task1) ? (t + 1) : t;
            const uint8_t* gt = g_xh + (size_t)tn * 16384;
            uint32_t dst = sb + SB_X0 + (uint32_t)(1 - p) * 16384;
            #pragma unroll
            for (int ii = 0; ii < 4; ++ii)
                cp16(dst + tid * 16 + ii * 4096, gt + tid * 16 + ii * 4096);
            CP_COMMIT();
        }
        CP_WAIT1();        // X[p] group done
        __syncthreads();   // X[p] visible to all; all warps past prior out phase

        if (b != bcur) {   // (re)load kv tile (hi only); readers wait at sync2
            const float2* kv2 = reinterpret_cast<const float2*>(g_kv) + (size_t)b * 8192;
            for (int i = tid; i < 8192; i += 256) {
                uint32_t f  = (uint32_t)(i >> 6);
                uint32_t cb = (uint32_t)(i & 63) * 4;
                float2 a = kv2[i];
                *(uint32_t*)(smem + SB_KVH + swz(f, cb)) = pack16(a.x, a.y);
            }
            bcur = b;
        }

        const uint32_t XHo = SB_X0 + (uint32_t)p * 16384;

        // ---- q projection (1-pass), warp tile 32x32 ----
        float pa[2][4][4];
        #pragma unroll
        for (int mb = 0; mb < 2; ++mb)
            #pragma unroll
            for (int nb = 0; nb < 4; ++nb)
                pa[mb][nb][0] = pa[mb][nb][1] = pa[mb][nb][2] = pa[mb][nb][3] = 0.f;
        {
            const uint32_t arow0 = (uint32_t)(m0 + (lane & 15));
            const uint32_t aco   = (uint32_t)((lane >> 4) & 1) * 16;
            const uint32_t brl   = (uint32_t)(lane & 15);
            #pragma unroll
            for (int ks = 0; ks < 8; ++ks) {
                uint32_t ah[2][4];
                uint32_t acb = (uint32_t)ks * 32 + aco;
                ldsm4(sb + XHo + swz(arow0,      acb), ah[0]);
                ldsm4(sb + XHo + swz(arow0 + 16, acb), ah[1]);
                #pragma unroll
                for (int ng = 0; ng < 2; ++ng) {
                    uint32_t br  = (uint32_t)ks * 16 + brl;
                    uint32_t bcb = (uint32_t)(c0 + ng * 16) * 2 + aco;
                    uint32_t bh[4];
                    ldsm4t(sb + SB_WQH + swz(br, bcb), bh);
                    mma1(pa[0][2 * ng], pa[0][2 * ng + 1], ah[0], bh);
                    mma1(pa[1][2 * ng], pa[1][2 * ng + 1], ah[1], bh);
                }
            }
        }
        // ---- epilogue: q = exp(.+bq) -> Q (hi only) ----
        #pragma unroll
        for (int mb = 0; mb < 2; ++mb) {
            int r0 = m0 + mb * 16 + er;
            #pragma unroll
            for (int nb = 0; nb < 4; ++nb) {
                int col = c0 + nb * 8 + ec;
                float b0 = bqr[2 * nb], b1 = bqr[2 * nb + 1];
                *(uint32_t*)(smem + SB_QH + swz((uint32_t)r0, (uint32_t)col * 2)) =
                    pack16(fexp(pa[mb][nb][0] + b0), fexp(pa[mb][nb][1] + b1));
                *(uint32_t*)(smem + SB_QH + swz((uint32_t)(r0 + 8), (uint32_t)col * 2)) =
                    pack16(fexp(pa[mb][nb][2] + b0), fexp(pa[mb][nb][3] + b1));
            }
        }
        __syncthreads();   // Q (and any reloaded KV) ready

        // ---- out = q @ kv (1-pass), warp tile 32x32 ----
        float oa[2][4][4];
        #pragma unroll
        for (int mb = 0; mb < 2; ++mb)
            #pragma unroll
            for (int nb = 0; nb < 4; ++nb)
                oa[mb][nb][0] = oa[mb][nb][1] = oa[mb][nb][2] = oa[mb][nb][3] = 0.f;
        {
            const uint32_t arow0 = (uint32_t)(m0 + (lane & 15));
            const uint32_t aco   = (uint32_t)((lane >> 4) & 1) * 16;
            const uint32_t brl   = (uint32_t)(lane & 15);
            #pragma unroll
            for (int ks = 0; ks < 8; ++ks) {
                uint32_t ah[2][4];
                uint32_t acb = (uint32_t)ks * 32 + aco;
                ldsm4(sb + SB_QH + swz(arow0,      acb), ah[0]);
                ldsm4(sb + SB_QH + swz(arow0 + 16, acb), ah[1]);
                #pragma unroll
                for (int ng = 0; ng < 2; ++ng) {
                    uint32_t br  = (uint32_t)ks * 16 + brl;
                    uint32_t bcb = (uint32_t)(c0 + ng * 16) * 2 + aco;
                    uint32_t bh[4];
                    ldsm4t(sb + SB_KVH + swz(br, bcb), bh);
                    mma1(oa[0][2 * ng], oa[0][2 * ng + 1], ah[0], bh);
                    mma1(oa[1][2 * ng], oa[1][2 * ng + 1], ah[1], bh);
                }
            }
        }
        // store
        float* og = out + (size_t)t * 8192;
        #pragma unroll
        for (int mb = 0; mb < 2; ++mb) {
            int r0 = m0 + mb * 16 + er;
            #pragma unroll
            for (int nb = 0; nb < 4; ++nb) {
                int col = c0 + nb * 8 + ec;
                *(float2*)(og + (size_t)r0 * 128 + col)       = make_float2(oa[mb][nb][0], oa[mb][nb][1]);
                *(float2*)(og + (size_t)(r0 + 8) * 128 + col) = make_float2(oa[mb][nb][2], oa[mb][nb][3]);
            }
        }
        p ^= 1;
    }
}

// ---------------------------------------------------------------------------
extern "C" void kernel_launch(void* const* d_in, const int* in_sizes, int n_in,
                              void* d_out, int out_size) {
    const float* x  = (const float*)d_in[0];
    const float* Wq = (const float*)d_in[1];
    const float* bq = (const float*)d_in[2];
    const float* Wk = (const float*)d_in[3];
    const float* bk = (const float*)d_in[4];
    const float* Wv = (const float*)d_in[5];
    const float* bv = (const float*)d_in[6];
    float* out = (float*)d_out;
    (void)in_sizes; (void)n_in; (void)out_size;

    cudaFuncSetAttribute(stageA, cudaFuncAttributeMaxDynamicSharedMemorySize, SA_SMEM);
    cudaFuncSetAttribute(stageB, cudaFuncAttributeMaxDynamicSharedMemorySize, SB_SMEM);

    zero_kv_kernel<<<256, 256>>>();
    stageA<<<GRIDA, 256, SA_SMEM>>>(x, Wk, bk, Wv, bv);
    stageB<<<GRIDB, 256, SB_SMEM>>>(x, Wq, bq, out);
}